// round 14
// baseline (speedup 1.0000x reference)
#include <cuda_runtime.h>
#include <math.h>

namespace {

typedef unsigned long long ull;

constexpr int T = 384;

__device__ __forceinline__ ull fma2(ull a, ull b, ull c) {
    ull d; asm("fma.rn.f32x2 %0, %1, %2, %3;" : "=l"(d) : "l"(a), "l"(b), "l"(c));
    return d;
}
__device__ __forceinline__ ull add2(ull a, ull b) {
    ull d; asm("add.rn.f32x2 %0, %1, %2;" : "=l"(d) : "l"(a), "l"(b));
    return d;
}
__device__ __forceinline__ ull pk(float lo, float hi) {
    ull r; asm("mov.b64 %0, {%1, %2};" : "=l"(r) : "f"(lo), "f"(hi));
    return r;
}
__device__ __forceinline__ float2 upk(ull u) {
    float2 f; asm("mov.b64 {%0, %1}, %2;" : "=f"(f.x), "=f"(f.y) : "l"(u));
    return f;
}

// One warp = 2 packed neurons (A=.lo, B=.hi). Three phases (identical math to
// the previous round):
//  P1: serial steps 0..191, lane owns m[0..5] for steps 6l..6l+5, 6-wide scatter.
//  P2: dense rectangle: all 192 published deltas into second-half slots.
//  P3: serial steps 192..383.
// NEW: weight table stored scrambled at u + (u>>2) (ull units) -> lane stride
// ~15 words, bank-conflict-free (was uniform 4-way). Per-lane parity-aligned
// base keeps the per-offset scramble term compile-time; 1 IADD per load.
__global__ void __launch_bounds__(32) flif_kernel(
    const float* __restrict__ I,     // [S, T]
    const float* __restrict__ W,     // [4999]
    float* __restrict__ out_spk,     // [S, T]
    float* __restrict__ out_trc)     // [S, T]
{
    // wr[idx], idx in [-384,383]: wr[idx<=0]=0, wr[idx>0]=W[4999-idx].
    // Entry u = idx+384 stored duplicated (w,w) at scrambled slot u + (u>>2).
    __shared__ ull wr2[960];
    __shared__ __align__(16) ull sIn[T];    // COEF*(I-1.75) packed (A,B)
    __shared__ __align__(16) ull strc[T];   // packed V trace
    __shared__ __align__(16) ull sdel[192]; // packed NEGATED deltas, steps 0..191

    const int lane = threadIdx.x;
    const int g    = blockIdx.x;
    const int sA   = 2 * g, sB = 2 * g + 1;

    for (int u = lane; u < 768; u += 32) {
        float v = (u >= 385) ? W[4999 - (u - 384)] : 0.0f;
        wr2[u + (u >> 2)] = pk(v, v);
    }

    const float COEF = (float)(pow(0.1, 0.15) * tgamma(2.0 - 0.15) / 0.5);

    const float* IA = I + (size_t)sA * T;
    const float* IB = I + (size_t)sB * T;
    {
        const float4* ia = reinterpret_cast<const float4*>(IA);
        const float4* ib = reinterpret_cast<const float4*>(IB);
        #pragma unroll
        for (int q = 0; q < 3; ++q) {
            float4 a = ia[lane + 32 * q], b = ib[lane + 32 * q];
            int t = (lane + 32 * q) * 4;
            sIn[t + 0] = pk(COEF * (a.x - 1.75f), COEF * (b.x - 1.75f));
            sIn[t + 1] = pk(COEF * (a.y - 1.75f), COEF * (b.y - 1.75f));
            sIn[t + 2] = pk(COEF * (a.z - 1.75f), COEF * (b.z - 1.75f));
            sIn[t + 3] = pk(COEF * (a.w - 1.75f), COEF * (b.w - 1.75f));
        }
    }
    const float rawA1 = IA[1];
    const float rawB1 = IB[1];
    __syncwarp();

    const float af = (float)(1.0 - (double)COEF * 0.025);   // 1 - COEF*GL
    const ull A2   = pk(af, af);
    const ull NEG1 = pk(-1.0f, -1.0f);

    // Per-lane parity-corrected scrambled byte offsets (kernel-constant regs).
    // base ub = 6(lane-2b)+384 has ub mod 4 == p; ub2 = ub - p is 4-aligned so
    // f(ub + o) = f(ub2) + q + (q>>2) with q = o + p compile-time-shaped.
    const int p = (lane & 1) << 1;
    int OFFb[17];
    #pragma unroll
    for (int o = -11; o <= 5; ++o) {
        int q = o + p;
        OFFb[o + 11] = (q + (q >> 2)) * 8;
    }
    const char* wrb = reinterpret_cast<const char*>(wr2);

    ull m[6];
    #pragma unroll
    for (int j = 0; j < 6; ++j) m[j] = 0ull;

    ull V, nrst, vhold, ndhold;

    // ===================== PHASE 1: serial steps 0..191 =====================
    // ---- block 0 (specials) ----
    {
        int ub2 = 6 * lane + 384 - p;
        const char* wb = wrb + ((ub2 + (ub2 >> 2)) << 3);
        ull wv[17];
        #pragma unroll
        for (int o = -11; o <= 5; ++o) wv[o + 11] = *(const ull*)(wb + OFFb[o + 11]);
        ull In[12];
        {
            const ulonglong2* ip = reinterpret_cast<const ulonglong2*>(&sIn[0]);
            #pragma unroll
            for (int q = 0; q < 6; ++q) { ulonglong2 pr = ip[q]; In[2*q] = pr.x; In[2*q+1] = pr.y; }
        }
        // step 0: V_pre=-70, V0=0 spikes -> Vn=-90; delta excluded (0)
        V = pk(-90.0f, -90.0f);
        vhold = V; ndhold = 0ull;
        // step 1: N==1 branch (V=-90 -> no spike/reset)
        {
            float2 v = upk(V);
            ull Vn = pk(v.x + 0.005f * (rawA1 / 0.025f - v.x),
                        v.y + 0.005f * (rawB1 / 0.025f - v.y));
            ull nd = fma2(Vn, NEG1, V);
            if (lane == 0) {
                ulonglong2 pr; pr.x = vhold;  pr.y = Vn;
                *reinterpret_cast<ulonglong2*>(&strc[0]) = pr;
                ulonglong2 pd; pd.x = ndhold; pd.y = nd;
                *reinterpret_cast<ulonglong2*>(&sdel[0]) = pd;
            }
            float2 vn = upk(Vn);
            nrst = pk(vn.x > -50.0f ? -20.0f : 0.0f,
                      vn.y > -50.0f ? -20.0f : 0.0f);
            V = Vn;
            #pragma unroll
            for (int j = 0; j < 6; ++j)
                m[j] = fma2(nd, wv[j - 1 + 11], m[j]);
        }
        // steps 2..11
        #pragma unroll
        for (int r = 2; r < 12; ++r) {
            ull mem = __shfl_sync(0xffffffffu, m[r % 6], (r < 6) ? 0 : 1);
            ull Vq = fma2(A2, V, In[r]);
            ull Vp = add2(Vq, mem);
            ull Vn = add2(Vp, nrst);
            ull nd = fma2(Vn, NEG1, V);
            float2 vn = upk(Vn);
            nrst = pk(vn.x > -50.0f ? -20.0f : 0.0f,
                      vn.y > -50.0f ? -20.0f : 0.0f);
            V = Vn;
            if (r & 1) {
                if (lane == 0) {
                    ulonglong2 pr; pr.x = vhold;  pr.y = Vn;
                    *reinterpret_cast<ulonglong2*>(&strc[r - 1]) = pr;
                    ulonglong2 pd; pd.x = ndhold; pd.y = nd;
                    *reinterpret_cast<ulonglong2*>(&sdel[r - 1]) = pd;
                }
            } else { vhold = Vn; ndhold = nd; }
            #pragma unroll
            for (int j = 0; j < 6; ++j)
                m[j] = fma2(nd, wv[j - r + 11], m[j]);
        }
    }
    // ---- blocks 1..15 ----
    #pragma unroll 1
    for (int b = 1; b < 16; ++b) {
        int ub2 = 6 * (lane - 2 * b) + 384 - p;
        const char* wb = wrb + ((ub2 + (ub2 >> 2)) << 3);
        ull wv[17];
        #pragma unroll
        for (int o = -11; o <= 5; ++o) wv[o + 11] = *(const ull*)(wb + OFFb[o + 11]);
        ull In[12];
        {
            const ulonglong2* ip = reinterpret_cast<const ulonglong2*>(&sIn[12 * b]);
            #pragma unroll
            for (int q = 0; q < 6; ++q) { ulonglong2 pr = ip[q]; In[2*q] = pr.x; In[2*q+1] = pr.y; }
        }
        const int o0 = 2 * b, o1 = 2 * b + 1;
        #pragma unroll
        for (int r = 0; r < 12; ++r) {
            ull mem = __shfl_sync(0xffffffffu, m[r % 6], (r < 6) ? o0 : o1);
            ull Vq = fma2(A2, V, In[r]);
            ull Vp = add2(Vq, mem);
            ull Vn = add2(Vp, nrst);
            ull nd = fma2(Vn, NEG1, V);
            float2 vn = upk(Vn);
            nrst = pk(vn.x > -50.0f ? -20.0f : 0.0f,
                      vn.y > -50.0f ? -20.0f : 0.0f);
            V = Vn;
            if (r & 1) {
                if (lane == 0) {
                    ulonglong2 pr; pr.x = vhold;  pr.y = Vn;
                    *reinterpret_cast<ulonglong2*>(&strc[12 * b + r - 1]) = pr;
                    ulonglong2 pd; pd.x = ndhold; pd.y = nd;
                    *reinterpret_cast<ulonglong2*>(&sdel[12 * b + r - 1]) = pd;
                }
            } else { vhold = Vn; ndhold = nd; }
            #pragma unroll
            for (int j = 0; j < 6; ++j)
                m[j] = fma2(nd, wv[j - r + 11], m[j]);
        }
    }
    __syncwarp();

    // ===================== PHASE 2: dense rectangle =====================
    // lane l now owns steps 192+6l..192+6l+5; add deltas 0..191 in order.
    #pragma unroll
    for (int j = 0; j < 6; ++j) m[j] = 0ull;
    #pragma unroll 1
    for (int b = 0; b < 16; ++b) {
        int ub2 = 6 * lane + 576 - 12 * b - p;
        const char* wb = wrb + ((ub2 + (ub2 >> 2)) << 3);
        ull wv[17];
        #pragma unroll
        for (int o = -11; o <= 5; ++o) wv[o + 11] = *(const ull*)(wb + OFFb[o + 11]);
        ull dd[12];
        {
            const ulonglong2* dp = reinterpret_cast<const ulonglong2*>(&sdel[12 * b]);
            #pragma unroll
            for (int q = 0; q < 6; ++q) { ulonglong2 pr = dp[q]; dd[2*q] = pr.x; dd[2*q+1] = pr.y; }
        }
        #pragma unroll
        for (int r = 0; r < 12; ++r) {
            #pragma unroll
            for (int j = 0; j < 6; ++j)
                m[j] = fma2(dd[r], wv[j - r + 11], m[j]);
        }
    }

    // ===================== PHASE 3: serial steps 192..383 =====================
    #pragma unroll 1
    for (int b = 0; b < 16; ++b) {
        int ub2 = 6 * (lane - 2 * b) + 384 - p;
        const char* wb = wrb + ((ub2 + (ub2 >> 2)) << 3);
        ull wv[17];
        #pragma unroll
        for (int o = -11; o <= 5; ++o) wv[o + 11] = *(const ull*)(wb + OFFb[o + 11]);
        ull In[12];
        {
            const ulonglong2* ip = reinterpret_cast<const ulonglong2*>(&sIn[192 + 12 * b]);
            #pragma unroll
            for (int q = 0; q < 6; ++q) { ulonglong2 pr = ip[q]; In[2*q] = pr.x; In[2*q+1] = pr.y; }
        }
        const int o0 = 2 * b, o1 = 2 * b + 1;
        #pragma unroll
        for (int r = 0; r < 12; ++r) {
            ull mem = __shfl_sync(0xffffffffu, m[r % 6], (r < 6) ? o0 : o1);
            ull Vq = fma2(A2, V, In[r]);
            ull Vp = add2(Vq, mem);
            ull Vn = add2(Vp, nrst);
            ull nd = fma2(Vn, NEG1, V);
            float2 vn = upk(Vn);
            nrst = pk(vn.x > -50.0f ? -20.0f : 0.0f,
                      vn.y > -50.0f ? -20.0f : 0.0f);
            V = Vn;
            if (r & 1) {
                if (lane == 0) {
                    ulonglong2 pr; pr.x = vhold; pr.y = Vn;
                    *reinterpret_cast<ulonglong2*>(&strc[192 + 12 * b + r - 1]) = pr;
                }
            } else vhold = Vn;
            #pragma unroll
            for (int j = 0; j < 6; ++j)
                m[j] = fma2(nd, wv[j - r + 11], m[j]);
        }
    }
    __syncwarp();

    // ---- outputs: spikes from stored trace (spike_n = V_{n-1} > -50), exact ----
    ull pv = (lane == 0) ? 0ull : strc[12 * lane - 1];
    float2 pp = upk(pv);
    float tA[12], tB[12], kA[12], kB[12];
    #pragma unroll
    for (int r = 0; r < 12; ++r) {
        float2 c = upk(strc[12 * lane + r]);
        tA[r] = c.x; tB[r] = c.y;
        kA[r] = (pp.x > -50.0f) ? 1.0f : 0.0f;
        kB[r] = (pp.y > -50.0f) ? 1.0f : 0.0f;
        pp = c;
    }
    const int bo = lane * 12;
    #pragma unroll
    for (int q = 0; q < 3; ++q) {
        reinterpret_cast<float4*>(out_spk + (size_t)sA * T + bo)[q] =
            make_float4(kA[4*q], kA[4*q+1], kA[4*q+2], kA[4*q+3]);
        reinterpret_cast<float4*>(out_spk + (size_t)sB * T + bo)[q] =
            make_float4(kB[4*q], kB[4*q+1], kB[4*q+2], kB[4*q+3]);
        reinterpret_cast<float4*>(out_trc + (size_t)sA * T + bo)[q] =
            make_float4(tA[4*q], tA[4*q+1], tA[4*q+2], tA[4*q+3]);
        reinterpret_cast<float4*>(out_trc + (size_t)sB * T + bo)[q] =
            make_float4(tB[4*q], tB[4*q+1], tB[4*q+2], tB[4*q+3]);
    }
}

} // namespace

extern "C" void kernel_launch(void* const* d_in, const int* in_sizes, int n_in,
                              void* d_out, int out_size) {
    const float* I = (const float*)d_in[0];     // [2048, 384]
    const float* W = (const float*)d_in[1];     // [4999]
    float* out = (float*)d_out;                 // [spk | trc]
    const int S = in_sizes[0] / T;              // 2048
    float* out_spk = out;
    float* out_trc = out + (size_t)S * T;
    flif_kernel<<<S / 2, 32>>>(I, W, out_spk, out_trc);
}

// round 15
// speedup vs baseline: 1.0583x; 1.0583x over previous
#include <cuda_runtime.h>
#include <math.h>

namespace {

typedef unsigned long long ull;

constexpr int T = 384;

__device__ __forceinline__ ull fma2(ull a, ull b, ull c) {
    ull d; asm("fma.rn.f32x2 %0, %1, %2, %3;" : "=l"(d) : "l"(a), "l"(b), "l"(c));
    return d;
}
__device__ __forceinline__ ull add2(ull a, ull b) {
    ull d; asm("add.rn.f32x2 %0, %1, %2;" : "=l"(d) : "l"(a), "l"(b));
    return d;
}
__device__ __forceinline__ ull pk(float lo, float hi) {
    ull r; asm("mov.b64 %0, {%1, %2};" : "=l"(r) : "f"(lo), "f"(hi));
    return r;
}
__device__ __forceinline__ float2 upk(ull u) {
    float2 f; asm("mov.b64 {%0, %1}, %2;" : "=f"(f.x), "=f"(f.y) : "l"(u));
    return f;
}

// One warp = 2 packed neurons (A=.lo, B=.hi). Three phases:
//  P1: serial steps 0..191. Lane l owns NEGATED accumulators m[0..5] for steps
//      6l..6l+5; 6-wide scatter; lane 0 publishes every delta to smem.
//  P2: m reinit; lane l owns steps 192+6l..+5; dense rectangle over the 192
//      published deltas (72 independent fma2 per 12-delta block).
//  P3: serial steps 192..383, 6-wide scatter.
// Weight table plain (u = idx+384, no scramble — scrambling measured slower).
// NEW vs best: #pragma unroll 2 on all three block loops so ptxas pipelines
// each block's 23 head loads under the previous block's compute.
__global__ void __launch_bounds__(32) flif_kernel(
    const float* __restrict__ I,     // [S, T]
    const float* __restrict__ W,     // [4999]
    float* __restrict__ out_spk,     // [S, T]
    float* __restrict__ out_trc)     // [S, T]
{
    __shared__ ull wr2[768];                // wr[idx] at u=idx+384; wr[idx<=0]=0
    __shared__ __align__(16) ull sIn[T];    // COEF*(I-1.75) packed (A,B)
    __shared__ __align__(16) ull strc[T];   // packed V trace
    __shared__ __align__(16) ull sdel[192]; // packed NEGATED deltas, steps 0..191

    const int lane = threadIdx.x;
    const int g    = blockIdx.x;
    const int sA   = 2 * g, sB = 2 * g + 1;

    for (int u = lane; u < 768; u += 32) {
        float v = (u >= 385) ? W[4999 - (u - 384)] : 0.0f;
        wr2[u] = pk(v, v);
    }

    const float COEF = (float)(pow(0.1, 0.15) * tgamma(2.0 - 0.15) / 0.5);

    const float* IA = I + (size_t)sA * T;
    const float* IB = I + (size_t)sB * T;
    {
        const float4* ia = reinterpret_cast<const float4*>(IA);
        const float4* ib = reinterpret_cast<const float4*>(IB);
        #pragma unroll
        for (int q = 0; q < 3; ++q) {
            float4 a = ia[lane + 32 * q], b = ib[lane + 32 * q];
            int t = (lane + 32 * q) * 4;
            sIn[t + 0] = pk(COEF * (a.x - 1.75f), COEF * (b.x - 1.75f));
            sIn[t + 1] = pk(COEF * (a.y - 1.75f), COEF * (b.y - 1.75f));
            sIn[t + 2] = pk(COEF * (a.z - 1.75f), COEF * (b.z - 1.75f));
            sIn[t + 3] = pk(COEF * (a.w - 1.75f), COEF * (b.w - 1.75f));
        }
    }
    const float rawA1 = IA[1];
    const float rawB1 = IB[1];
    __syncwarp();

    const float af = (float)(1.0 - (double)COEF * 0.025);   // 1 - COEF*GL
    const ull A2   = pk(af, af);
    const ull NEG1 = pk(-1.0f, -1.0f);

    ull m[6];
    #pragma unroll
    for (int j = 0; j < 6; ++j) m[j] = 0ull;

    ull V, nrst, vhold, ndhold;

    // ===================== PHASE 1: serial steps 0..191 =====================
    // ---- block 0 (specials) ----
    {
        const ull* wp = wr2 + (6 * lane + 384);
        ull wv[17];
        #pragma unroll
        for (int o = -11; o <= 5; ++o) wv[o + 11] = wp[o];
        ull In[12];
        {
            const ulonglong2* ip = reinterpret_cast<const ulonglong2*>(&sIn[0]);
            #pragma unroll
            for (int q = 0; q < 6; ++q) { ulonglong2 p = ip[q]; In[2*q] = p.x; In[2*q+1] = p.y; }
        }
        // step 0: V_pre=-70, V0=0 spikes -> Vn=-90; delta excluded (0)
        V = pk(-90.0f, -90.0f);
        vhold = V; ndhold = 0ull;
        // step 1: N==1 branch (V=-90 -> no spike/reset)
        {
            float2 v = upk(V);
            ull Vn = pk(v.x + 0.005f * (rawA1 / 0.025f - v.x),
                        v.y + 0.005f * (rawB1 / 0.025f - v.y));
            ull nd = fma2(Vn, NEG1, V);
            if (lane == 0) {
                ulonglong2 pr; pr.x = vhold;  pr.y = Vn;
                *reinterpret_cast<ulonglong2*>(&strc[0]) = pr;
                ulonglong2 pd; pd.x = ndhold; pd.y = nd;
                *reinterpret_cast<ulonglong2*>(&sdel[0]) = pd;
            }
            float2 vn = upk(Vn);
            nrst = pk(vn.x > -50.0f ? -20.0f : 0.0f,
                      vn.y > -50.0f ? -20.0f : 0.0f);
            V = Vn;
            #pragma unroll
            for (int j = 0; j < 6; ++j)
                m[j] = fma2(nd, wv[j - 1 + 11], m[j]);
        }
        // steps 2..11
        #pragma unroll
        for (int r = 2; r < 12; ++r) {
            ull mem = __shfl_sync(0xffffffffu, m[r % 6], (r < 6) ? 0 : 1);
            ull Vq = fma2(A2, V, In[r]);
            ull Vp = add2(Vq, mem);
            ull Vn = add2(Vp, nrst);
            ull nd = fma2(Vn, NEG1, V);
            float2 vn = upk(Vn);
            nrst = pk(vn.x > -50.0f ? -20.0f : 0.0f,
                      vn.y > -50.0f ? -20.0f : 0.0f);
            V = Vn;
            if (r & 1) {
                if (lane == 0) {
                    ulonglong2 pr; pr.x = vhold;  pr.y = Vn;
                    *reinterpret_cast<ulonglong2*>(&strc[r - 1]) = pr;
                    ulonglong2 pd; pd.x = ndhold; pd.y = nd;
                    *reinterpret_cast<ulonglong2*>(&sdel[r - 1]) = pd;
                }
            } else { vhold = Vn; ndhold = nd; }
            #pragma unroll
            for (int j = 0; j < 6; ++j)
                m[j] = fma2(nd, wv[j - r + 11], m[j]);
        }
    }
    // ---- blocks 1..15 ----
    #pragma unroll 2
    for (int b = 1; b < 16; ++b) {
        const ull* wp = wr2 + (6 * (lane - 2 * b) + 384);
        ull wv[17];
        #pragma unroll
        for (int o = -11; o <= 5; ++o) wv[o + 11] = wp[o];
        ull In[12];
        {
            const ulonglong2* ip = reinterpret_cast<const ulonglong2*>(&sIn[12 * b]);
            #pragma unroll
            for (int q = 0; q < 6; ++q) { ulonglong2 p = ip[q]; In[2*q] = p.x; In[2*q+1] = p.y; }
        }
        const int o0 = 2 * b, o1 = 2 * b + 1;
        #pragma unroll
        for (int r = 0; r < 12; ++r) {
            ull mem = __shfl_sync(0xffffffffu, m[r % 6], (r < 6) ? o0 : o1);
            ull Vq = fma2(A2, V, In[r]);
            ull Vp = add2(Vq, mem);
            ull Vn = add2(Vp, nrst);
            ull nd = fma2(Vn, NEG1, V);
            float2 vn = upk(Vn);
            nrst = pk(vn.x > -50.0f ? -20.0f : 0.0f,
                      vn.y > -50.0f ? -20.0f : 0.0f);
            V = Vn;
            if (r & 1) {
                if (lane == 0) {
                    ulonglong2 pr; pr.x = vhold;  pr.y = Vn;
                    *reinterpret_cast<ulonglong2*>(&strc[12 * b + r - 1]) = pr;
                    ulonglong2 pd; pd.x = ndhold; pd.y = nd;
                    *reinterpret_cast<ulonglong2*>(&sdel[12 * b + r - 1]) = pd;
                }
            } else { vhold = Vn; ndhold = nd; }
            #pragma unroll
            for (int j = 0; j < 6; ++j)
                m[j] = fma2(nd, wv[j - r + 11], m[j]);
        }
    }
    __syncwarp();

    // ===================== PHASE 2: dense rectangle =====================
    // lane l now owns steps 192+6l..192+6l+5; add deltas 0..191 in order.
    #pragma unroll
    for (int j = 0; j < 6; ++j) m[j] = 0ull;
    #pragma unroll 2
    for (int b = 0; b < 16; ++b) {
        const ull* wp = wr2 + (6 * lane + 576 - 12 * b);
        ull wv[17];
        #pragma unroll
        for (int o = -11; o <= 5; ++o) wv[o + 11] = wp[o];
        ull dd[12];
        {
            const ulonglong2* dp = reinterpret_cast<const ulonglong2*>(&sdel[12 * b]);
            #pragma unroll
            for (int q = 0; q < 6; ++q) { ulonglong2 p = dp[q]; dd[2*q] = p.x; dd[2*q+1] = p.y; }
        }
        #pragma unroll
        for (int r = 0; r < 12; ++r) {
            #pragma unroll
            for (int j = 0; j < 6; ++j)
                m[j] = fma2(dd[r], wv[j - r + 11], m[j]);
        }
    }

    // ===================== PHASE 3: serial steps 192..383 =====================
    #pragma unroll 2
    for (int b = 0; b < 16; ++b) {
        const ull* wp = wr2 + (6 * (lane - 2 * b) + 384);
        ull wv[17];
        #pragma unroll
        for (int o = -11; o <= 5; ++o) wv[o + 11] = wp[o];
        ull In[12];
        {
            const ulonglong2* ip = reinterpret_cast<const ulonglong2*>(&sIn[192 + 12 * b]);
            #pragma unroll
            for (int q = 0; q < 6; ++q) { ulonglong2 p = ip[q]; In[2*q] = p.x; In[2*q+1] = p.y; }
        }
        const int o0 = 2 * b, o1 = 2 * b + 1;
        #pragma unroll
        for (int r = 0; r < 12; ++r) {
            ull mem = __shfl_sync(0xffffffffu, m[r % 6], (r < 6) ? o0 : o1);
            ull Vq = fma2(A2, V, In[r]);
            ull Vp = add2(Vq, mem);
            ull Vn = add2(Vp, nrst);
            ull nd = fma2(Vn, NEG1, V);
            float2 vn = upk(Vn);
            nrst = pk(vn.x > -50.0f ? -20.0f : 0.0f,
                      vn.y > -50.0f ? -20.0f : 0.0f);
            V = Vn;
            if (r & 1) {
                if (lane == 0) {
                    ulonglong2 pr; pr.x = vhold; pr.y = Vn;
                    *reinterpret_cast<ulonglong2*>(&strc[192 + 12 * b + r - 1]) = pr;
                }
            } else vhold = Vn;
            #pragma unroll
            for (int j = 0; j < 6; ++j)
                m[j] = fma2(nd, wv[j - r + 11], m[j]);
        }
    }
    __syncwarp();

    // ---- outputs: spikes from stored trace (spike_n = V_{n-1} > -50), exact ----
    ull pv = (lane == 0) ? 0ull : strc[12 * lane - 1];
    float2 pp = upk(pv);
    float tA[12], tB[12], kA[12], kB[12];
    #pragma unroll
    for (int r = 0; r < 12; ++r) {
        float2 c = upk(strc[12 * lane + r]);
        tA[r] = c.x; tB[r] = c.y;
        kA[r] = (pp.x > -50.0f) ? 1.0f : 0.0f;
        kB[r] = (pp.y > -50.0f) ? 1.0f : 0.0f;
        pp = c;
    }
    const int bo = lane * 12;
    #pragma unroll
    for (int q = 0; q < 3; ++q) {
        reinterpret_cast<float4*>(out_spk + (size_t)sA * T + bo)[q] =
            make_float4(kA[4*q], kA[4*q+1], kA[4*q+2], kA[4*q+3]);
        reinterpret_cast<float4*>(out_spk + (size_t)sB * T + bo)[q] =
            make_float4(kB[4*q], kB[4*q+1], kB[4*q+2], kB[4*q+3]);
        reinterpret_cast<float4*>(out_trc + (size_t)sA * T + bo)[q] =
            make_float4(tA[4*q], tA[4*q+1], tA[4*q+2], tA[4*q+3]);
        reinterpret_cast<float4*>(out_trc + (size_t)sB * T + bo)[q] =
            make_float4(tB[4*q], tB[4*q+1], tB[4*q+2], tB[4*q+3]);
    }
}

} // namespace

extern "C" void kernel_launch(void* const* d_in, const int* in_sizes, int n_in,
                              void* d_out, int out_size) {
    const float* I = (const float*)d_in[0];     // [2048, 384]
    const float* W = (const float*)d_in[1];     // [4999]
    float* out = (float*)d_out;                 // [spk | trc]
    const int S = in_sizes[0] / T;              // 2048
    float* out_spk = out;
    float* out_trc = out + (size_t)S * T;
    flif_kernel<<<S / 2, 32>>>(I, W, out_spk, out_trc);
}